// round 8
// baseline (speedup 1.0000x reference)
#include <cuda_runtime.h>
#include <cuda_fp16.h>
#include <cstdint>

// GAPooling: out[b,n,c] = (1/K) * sum_k x[b, idx[b,n,k], c]
// x [16,4096,64] fp32, idx [16,4096,32] int32, out fp32.
//
// Stage 1: x -> fp16 table (8 MB). Row = 128 B = one L1 line.
// Stage 2: warp per point. Index delivery via BROADCAST LDG.128 (all lanes
//          read the same 16 B -> 1 wavefront, 4 indices to every lane) --
//          zero SHFLs on the LSU crossbar. Each gather is one LDG.32 per
//          warp covering exactly one 128 B line (lane c reads the half2 of
//          channels {2c,2c+1} of row j) at the 1.0 cyc cross-LDG wavefront
//          rate (no within-LDG replays). 8 independent gathers in flight
//          per block of indices. half2 chains of 4, fp32 spill per chain,
//          direct float2 store (no cross-lane reduction).

static constexpr int B = 16;
static constexpr int N = 4096;
static constexpr int C = 64;
static constexpr int K = 32;

__device__ __half g_xh[(size_t)B * N * C];   // 8 MB fp16 table

__global__ __launch_bounds__(256) void cvt_kernel(const float* __restrict__ x)
{
    const int t = blockIdx.x * blockDim.x + threadIdx.x;   // B*N*C/8 threads
    const float4* __restrict__ xi = reinterpret_cast<const float4*>(x);
    float4 a = xi[2 * t];
    float4 b = xi[2 * t + 1];
    __half2 h[4];
    h[0] = __floats2half2_rn(a.x, a.y);
    h[1] = __floats2half2_rn(a.z, a.w);
    h[2] = __floats2half2_rn(b.x, b.y);
    h[3] = __floats2half2_rn(b.z, b.w);
    reinterpret_cast<uint4*>(g_xh)[t] = *reinterpret_cast<uint4*>(h);
}

__global__ __launch_bounds__(256) void gap_f16_kernel(
    const int* __restrict__ idx,
    float* __restrict__ out)
{
    const int warp_global = (blockIdx.x * blockDim.x + threadIdx.x) >> 5;
    const int lane = threadIdx.x & 31;
    if (warp_global >= B * N) return;

    const int b = warp_global >> 12;           // N = 4096 = 2^12

    // Warp-uniform base of this point's 32 indices (no lane term!)
    const int4* __restrict__ idx_w =
        reinterpret_cast<const int4*>(idx + (size_t)warp_global * K);

    // lane c owns channels {2c, 2c+1}; row j lives at xb2 + j*32
    const __half2* __restrict__ xb2 = reinterpret_cast<const __half2*>(
        g_xh + (size_t)b * N * C) + lane;

    float2 acc = make_float2(0.f, 0.f);

    #pragma unroll
    for (int blk = 0; blk < 4; blk++) {
        // Two broadcast LDG.128: 8 indices into registers of every lane
        const int4 i0 = __ldg(idx_w + blk * 2);
        const int4 i1 = __ldg(idx_w + blk * 2 + 1);

        // 8 independent single-line gathers in flight
        const __half2 g0 = __ldg(xb2 + i0.x * 32);
        const __half2 g1 = __ldg(xb2 + i0.y * 32);
        const __half2 g2 = __ldg(xb2 + i0.z * 32);
        const __half2 g3 = __ldg(xb2 + i0.w * 32);
        const __half2 g4 = __ldg(xb2 + i1.x * 32);
        const __half2 g5 = __ldg(xb2 + i1.y * 32);
        const __half2 g6 = __ldg(xb2 + i1.z * 32);
        const __half2 g7 = __ldg(xb2 + i1.w * 32);

        // Two independent chains of 4 (bounds fp16 rounding), fp32 spill
        const __half2 ha = __hadd2(__hadd2(g0, g1), __hadd2(g2, g3));
        const __half2 hb = __hadd2(__hadd2(g4, g5), __hadd2(g6, g7));
        const float2 fa = __half22float2(ha);
        const float2 fb = __half22float2(hb);
        acc.x += fa.x + fb.x;
        acc.y += fa.y + fb.y;
    }

    const float inv_k = 1.0f / (float)K;
    float2 r;
    r.x = acc.x * inv_k;
    r.y = acc.y * inv_k;
    reinterpret_cast<float2*>(out)[(size_t)warp_global * (C / 2) + lane] = r;
}

extern "C" void kernel_launch(void* const* d_in, const int* in_sizes, int n_in,
                              void* d_out, int out_size)
{
    // Select inputs by element count (ordering-proof):
    //   x:   B*N*C = 4,194,304 ; idx: B*N*K = 2,097,152
    const float* x = nullptr;
    const int* idx = nullptr;
    for (int i = 0; i < n_in; i++) {
        if (in_sizes[i] == B * N * C) x = (const float*)d_in[i];
        else if (in_sizes[i] == B * N * K) idx = (const int*)d_in[i];
    }
    if (!x) x = (const float*)d_in[0];
    if (!idx) idx = (const int*)d_in[1];
    float* out = (float*)d_out;

    // Stage 1: fp32 -> fp16 table
    const int cvt_threads = (B * N * C) / 8;               // 524288
    cvt_kernel<<<cvt_threads / 256, 256>>>(x);

    // Stage 2: gather-mean, one warp per point
    const int total_warps = B * N;                          // 65536
    gap_f16_kernel<<<(total_warps * 32) / 256, 256>>>(idx, out);
}

// round 9
// speedup vs baseline: 1.2730x; 1.2730x over previous
#include <cuda_runtime.h>
#include <cuda_fp16.h>
#include <cstdint>

// GAPooling: out[b,n,c] = (1/K) * sum_k x[b, idx[b,n,k], c]
// x [16,4096,64] fp32, idx [16,4096,32] int32, out fp32.
//
// Stage 1: x -> fp16 table (8 MB). Row = 128 B = one L1 line.
// Stage 2: warp per point. Gathers are LDG.128 covering 4 whole rows
//          (slot r = lane>>3, chunk cq = lane&7) -- max bytes per LDG
//          instruction (LSU issue floor is per-instruction). Index
//          delivery: each lane LDGs its own slot's index directly
//          (idx[warp*32 + 4i + r]); all 8 such loads share one 128 B L1
//          line -> ~1 fill + cheap hits, ZERO shuffles on the LSU/MIO
//          pipe. hadd2 chains of 4 with fp32 spill, butterfly reduce
//          over r-groups, fp32 store.

static constexpr int B = 16;
static constexpr int N = 4096;
static constexpr int C = 64;
static constexpr int K = 32;

__device__ __half g_xh[(size_t)B * N * C];   // 8 MB fp16 table

__global__ __launch_bounds__(256) void cvt_kernel(const float* __restrict__ x)
{
    const int t = blockIdx.x * blockDim.x + threadIdx.x;   // B*N*C/8 threads
    const float4* __restrict__ xi = reinterpret_cast<const float4*>(x);
    float4 a = xi[2 * t];
    float4 b = xi[2 * t + 1];
    __half2 h[4];
    h[0] = __floats2half2_rn(a.x, a.y);
    h[1] = __floats2half2_rn(a.z, a.w);
    h[2] = __floats2half2_rn(b.x, b.y);
    h[3] = __floats2half2_rn(b.z, b.w);
    reinterpret_cast<uint4*>(g_xh)[t] = *reinterpret_cast<uint4*>(h);
}

__global__ __launch_bounds__(256) void gap_f16_kernel(
    const int* __restrict__ idx,
    float* __restrict__ out)
{
    const int warp_global = (blockIdx.x * blockDim.x + threadIdx.x) >> 5;
    const int lane = threadIdx.x & 31;
    if (warp_global >= B * N) return;

    const int b  = warp_global >> 12;          // N = 4096 = 2^12
    const int r  = lane >> 3;                  // 0..3  (row slot within LDG)
    const int cq = lane & 7;                   // 0..7  (16 B channel chunk)

    // This lane's index stream: positions r, r+4, ..., r+28 of this point's
    // 32 indices. All 8 loads live in one 128 B line.
    const int* __restrict__ iw = idx + (size_t)warp_global * K + r;

    const __half* __restrict__ xb = g_xh + (size_t)b * N * C + cq * 8;

    float acc[8];
    #pragma unroll
    for (int c = 0; c < 8; c++) acc[c] = 0.f;

    #pragma unroll
    for (int blk = 0; blk < 2; blk++) {
        __half2 hacc[4];
        #pragma unroll
        for (int q = 0; q < 4; q++) hacc[q] = __half2half2(__ushort_as_half(0));

        #pragma unroll
        for (int i = 0; i < 4; i++) {
            const int j = __ldg(iw + (blk * 4 + i) * 4);   // slot r, quad i
            const float4 raw = *reinterpret_cast<const float4*>(
                xb + (size_t)j * C);                        // 16 B = 8 halves
            const __half2* h2 = reinterpret_cast<const __half2*>(&raw);
            #pragma unroll
            for (int q = 0; q < 4; q++)
                hacc[q] = __hadd2(hacc[q], h2[q]);
        }

        #pragma unroll
        for (int q = 0; q < 4; q++) {
            const float2 f = __half22float2(hacc[q]);
            acc[2 * q]     += f.x;
            acc[2 * q + 1] += f.y;
        }
    }

    // reduce the 4 r-groups (lane bits 3,4) in fp32
    #pragma unroll
    for (int c = 0; c < 8; c++) {
        acc[c] += __shfl_xor_sync(0xffffffffu, acc[c], 8);
        acc[c] += __shfl_xor_sync(0xffffffffu, acc[c], 16);
    }

    if (r == 0) {
        const float inv_k = 1.0f / (float)K;
        float4 o0, o1;
        o0.x = acc[0] * inv_k; o0.y = acc[1] * inv_k;
        o0.z = acc[2] * inv_k; o0.w = acc[3] * inv_k;
        o1.x = acc[4] * inv_k; o1.y = acc[5] * inv_k;
        o1.z = acc[6] * inv_k; o1.w = acc[7] * inv_k;
        float4* op = reinterpret_cast<float4*>(
            out + (size_t)warp_global * C + cq * 8);
        op[0] = o0;
        op[1] = o1;
    }
}

extern "C" void kernel_launch(void* const* d_in, const int* in_sizes, int n_in,
                              void* d_out, int out_size)
{
    // Select inputs by element count (ordering-proof):
    //   x:   B*N*C = 4,194,304 ; idx: B*N*K = 2,097,152
    const float* x = nullptr;
    const int* idx = nullptr;
    for (int i = 0; i < n_in; i++) {
        if (in_sizes[i] == B * N * C) x = (const float*)d_in[i];
        else if (in_sizes[i] == B * N * K) idx = (const int*)d_in[i];
    }
    if (!x) x = (const float*)d_in[0];
    if (!idx) idx = (const int*)d_in[1];
    float* out = (float*)d_out;

    // Stage 1: fp32 -> fp16 table
    const int cvt_threads = (B * N * C) / 8;               // 524288
    cvt_kernel<<<cvt_threads / 256, 256>>>(x);

    // Stage 2: gather-mean, one warp per point
    const int total_warps = B * N;                          // 65536
    gap_f16_kernel<<<(total_warps * 32) / 256, 256>>>(idx, out);
}

// round 10
// speedup vs baseline: 1.3513x; 1.0615x over previous
#include <cuda_runtime.h>
#include <cuda_fp16.h>
#include <cstdint>

// GAPooling: out[b,n,c] = (1/K) * sum_k x[b, idx[b,n,k], c]
// x [16,4096,64] fp32, idx [16,4096,32] int32, out fp32.
//
// Stage 1: x -> fp16 table (8 MB). Row = 128 B = one L1 line. DRAM-floor
//          bound (~3.6 us for 24 MB).
// Stage 2: warp per point; 8x LDG.128 gathers (4 rows each), per-lane idx
//          loads (one 128 B line per warp's index stream, zero SHFL on the
//          LSU path), hadd2 chains of 4 with fp32 spill, butterfly reduce.
//          Sits at the L1 wavefront-replay equilibrium (~21 us).
//
// NEW: chunk-pipelined launch. gap for batches [4c,4c+4) depends only on
// cvt of those batches. cvt chunks run on the capture stream, gap chunks
// on a forked stream gated by events -> cvt_1..3 hide under gap_0,
// collapsing the serial cvt tail (~2.7 us saved).

static constexpr int B = 16;
static constexpr int N = 4096;
static constexpr int C = 64;
static constexpr int K = 32;

static constexpr int NCHUNK = 4;
static constexpr int CHUNK_B = B / NCHUNK;                       // 4 batches
static constexpr int CHUNK_X8 = CHUNK_B * N * C / 8;             // cvt threads/chunk
static constexpr int CHUNK_WARPS = CHUNK_B * N;                  // 16384

__device__ __half g_xh[(size_t)B * N * C];   // 8 MB fp16 table

__global__ __launch_bounds__(256) void cvt_kernel(const float* __restrict__ x,
                                                  int chunk)
{
    const size_t t = (size_t)chunk * CHUNK_X8
                   + blockIdx.x * blockDim.x + threadIdx.x;
    const float4* __restrict__ xi = reinterpret_cast<const float4*>(x);
    float4 a = xi[2 * t];
    float4 b = xi[2 * t + 1];
    __half2 h[4];
    h[0] = __floats2half2_rn(a.x, a.y);
    h[1] = __floats2half2_rn(a.z, a.w);
    h[2] = __floats2half2_rn(b.x, b.y);
    h[3] = __floats2half2_rn(b.z, b.w);
    reinterpret_cast<uint4*>(g_xh)[t] = *reinterpret_cast<uint4*>(h);
}

__global__ __launch_bounds__(256) void gap_f16_kernel(
    const int* __restrict__ idx,
    float* __restrict__ out,
    int chunk)
{
    const int warp_global = chunk * CHUNK_WARPS
                          + ((blockIdx.x * blockDim.x + threadIdx.x) >> 5);
    const int lane = threadIdx.x & 31;

    const int b  = warp_global >> 12;          // N = 4096 = 2^12
    const int r  = lane >> 3;                  // 0..3  (row slot within LDG)
    const int cq = lane & 7;                   // 0..7  (16 B channel chunk)

    // This lane's index stream: positions r, r+4, ..., r+28. One 128 B line.
    const int* __restrict__ iw = idx + (size_t)warp_global * K + r;

    const __half* __restrict__ xb = g_xh + (size_t)b * N * C + cq * 8;

    float acc[8];
    #pragma unroll
    for (int c = 0; c < 8; c++) acc[c] = 0.f;

    #pragma unroll
    for (int blk = 0; blk < 2; blk++) {
        __half2 hacc[4];
        #pragma unroll
        for (int q = 0; q < 4; q++) hacc[q] = __half2half2(__ushort_as_half(0));

        #pragma unroll
        for (int i = 0; i < 4; i++) {
            const int j = __ldg(iw + (blk * 4 + i) * 4);   // slot r, quad i
            const float4 raw = *reinterpret_cast<const float4*>(
                xb + (size_t)j * C);                        // 16 B = 8 halves
            const __half2* h2 = reinterpret_cast<const __half2*>(&raw);
            #pragma unroll
            for (int q = 0; q < 4; q++)
                hacc[q] = __hadd2(hacc[q], h2[q]);
        }

        #pragma unroll
        for (int q = 0; q < 4; q++) {
            const float2 f = __half22float2(hacc[q]);
            acc[2 * q]     += f.x;
            acc[2 * q + 1] += f.y;
        }
    }

    // reduce the 4 r-groups (lane bits 3,4) in fp32
    #pragma unroll
    for (int c = 0; c < 8; c++) {
        acc[c] += __shfl_xor_sync(0xffffffffu, acc[c], 8);
        acc[c] += __shfl_xor_sync(0xffffffffu, acc[c], 16);
    }

    if (r == 0) {
        const float inv_k = 1.0f / (float)K;
        float4 o0, o1;
        o0.x = acc[0] * inv_k; o0.y = acc[1] * inv_k;
        o0.z = acc[2] * inv_k; o0.w = acc[3] * inv_k;
        o1.x = acc[4] * inv_k; o1.y = acc[5] * inv_k;
        o1.z = acc[6] * inv_k; o1.w = acc[7] * inv_k;
        float4* op = reinterpret_cast<float4*>(
            out + (size_t)warp_global * C + cq * 8);
        op[0] = o0;
        op[1] = o1;
    }
}

extern "C" void kernel_launch(void* const* d_in, const int* in_sizes, int n_in,
                              void* d_out, int out_size)
{
    // Select inputs by element count (ordering-proof):
    //   x:   B*N*C = 4,194,304 ; idx: B*N*K = 2,097,152
    const float* x = nullptr;
    const int* idx = nullptr;
    for (int i = 0; i < n_in; i++) {
        if (in_sizes[i] == B * N * C) x = (const float*)d_in[i];
        else if (in_sizes[i] == B * N * K) idx = (const int*)d_in[i];
    }
    if (!x) x = (const float*)d_in[0];
    if (!idx) idx = (const int*)d_in[1];
    float* out = (float*)d_out;

    // One-time side stream + events (no device memory involved).
    static cudaStream_t s2 = nullptr;
    static cudaEvent_t ev[NCHUNK];
    static cudaEvent_t ev_join = nullptr;
    if (!s2) {
        cudaStreamCreateWithFlags(&s2, cudaStreamNonBlocking);
        for (int c = 0; c < NCHUNK; c++)
            cudaEventCreateWithFlags(&ev[c], cudaEventDisableTiming);
        cudaEventCreateWithFlags(&ev_join, cudaEventDisableTiming);
    }

    // Legacy/default stream (the one the harness captures).
    cudaStream_t s = 0;

    // Pipelined chunks: cvt_c on s, gap_c on s2 gated by ev[c].
    for (int c = 0; c < NCHUNK; c++) {
        cvt_kernel<<<CHUNK_X8 / 256, 256, 0, s>>>(x, c);
        cudaEventRecord(ev[c], s);
        cudaStreamWaitEvent(s2, ev[c], 0);
        gap_f16_kernel<<<(CHUNK_WARPS * 32) / 256, 256, 0, s2>>>(idx, out, c);
    }

    // Join the side stream back into the captured stream.
    cudaEventRecord(ev_join, s2);
    cudaStreamWaitEvent(s, ev_join, 0);
}

// round 11
// speedup vs baseline: 1.5702x; 1.1620x over previous
#include <cuda_runtime.h>
#include <cuda_fp16.h>
#include <cstdint>

// GAPooling: out[b,n,c] = (1/K) * sum_k x[b, idx[b,n,k], c]
// x [16,4096,64] fp32, idx [16,4096,32] int32, out fp32.
//
// Stage 1: x -> fp16 table (8 MB). Row = 128 B = one L1 line.
// Stage 2: warp per point; 8x LDG.128 gathers (4 rows each) with
//          L1::evict_last (table rows are reused ~32x each -> pin them in
//          L1), per-lane idx loads with L1::evict_first (one-shot stream,
//          don't displace table lines). hadd2 chains of 4 with fp32 spill,
//          butterfly reduce over r-groups, fp32 store.
// Flat launch (R10 showed chunk-pipelining inflates gap chunks by ~66%).

static constexpr int B = 16;
static constexpr int N = 4096;
static constexpr int C = 64;
static constexpr int K = 32;

__device__ __half g_xh[(size_t)B * N * C];   // 8 MB fp16 table

__global__ __launch_bounds__(256) void cvt_kernel(const float* __restrict__ x)
{
    const int t = blockIdx.x * blockDim.x + threadIdx.x;   // B*N*C/8 threads
    const float4* __restrict__ xi = reinterpret_cast<const float4*>(x);
    float4 a = xi[2 * t];
    float4 b = xi[2 * t + 1];
    __half2 h[4];
    h[0] = __floats2half2_rn(a.x, a.y);
    h[1] = __floats2half2_rn(a.z, a.w);
    h[2] = __floats2half2_rn(b.x, b.y);
    h[3] = __floats2half2_rn(b.z, b.w);
    reinterpret_cast<uint4*>(g_xh)[t] = *reinterpret_cast<uint4*>(h);
}

// Table gather: 16 B, keep resident in L1 (heavy reuse).
__device__ __forceinline__ float4 ldg_evict_last_v4(const void* p)
{
    float4 v;
    asm volatile("ld.global.nc.L1::evict_last.v4.f32 {%0,%1,%2,%3}, [%4];"
                 : "=f"(v.x), "=f"(v.y), "=f"(v.z), "=f"(v.w)
                 : "l"(p));
    return v;
}

// Index load: 4 B, one-shot stream, evict first.
__device__ __forceinline__ int ldg_evict_first_s32(const void* p)
{
    int v;
    asm volatile("ld.global.nc.L1::evict_first.b32 %0, [%1];"
                 : "=r"(v) : "l"(p));
    return v;
}

__global__ __launch_bounds__(256) void gap_f16_kernel(
    const int* __restrict__ idx,
    float* __restrict__ out)
{
    const int warp_global = (blockIdx.x * blockDim.x + threadIdx.x) >> 5;
    const int lane = threadIdx.x & 31;
    if (warp_global >= B * N) return;

    const int b  = warp_global >> 12;          // N = 4096 = 2^12
    const int r  = lane >> 3;                  // 0..3  (row slot within LDG)
    const int cq = lane & 7;                   // 0..7  (16 B channel chunk)

    // This lane's index stream: positions r, r+4, ..., r+28. One 128 B line.
    const int* __restrict__ iw = idx + (size_t)warp_global * K + r;

    const __half* __restrict__ xb = g_xh + (size_t)b * N * C + cq * 8;

    float acc[8];
    #pragma unroll
    for (int c = 0; c < 8; c++) acc[c] = 0.f;

    #pragma unroll
    for (int blk = 0; blk < 2; blk++) {
        __half2 hacc[4];
        #pragma unroll
        for (int q = 0; q < 4; q++) hacc[q] = __half2half2(__ushort_as_half(0));

        #pragma unroll
        for (int i = 0; i < 4; i++) {
            const int j = ldg_evict_first_s32(iw + (blk * 4 + i) * 4);
            const float4 raw = ldg_evict_last_v4(xb + (size_t)j * C);
            const __half2* h2 = reinterpret_cast<const __half2*>(&raw);
            #pragma unroll
            for (int q = 0; q < 4; q++)
                hacc[q] = __hadd2(hacc[q], h2[q]);
        }

        #pragma unroll
        for (int q = 0; q < 4; q++) {
            const float2 f = __half22float2(hacc[q]);
            acc[2 * q]     += f.x;
            acc[2 * q + 1] += f.y;
        }
    }

    // reduce the 4 r-groups (lane bits 3,4) in fp32
    #pragma unroll
    for (int c = 0; c < 8; c++) {
        acc[c] += __shfl_xor_sync(0xffffffffu, acc[c], 8);
        acc[c] += __shfl_xor_sync(0xffffffffu, acc[c], 16);
    }

    if (r == 0) {
        const float inv_k = 1.0f / (float)K;
        float4 o0, o1;
        o0.x = acc[0] * inv_k; o0.y = acc[1] * inv_k;
        o0.z = acc[2] * inv_k; o0.w = acc[3] * inv_k;
        o1.x = acc[4] * inv_k; o1.y = acc[5] * inv_k;
        o1.z = acc[6] * inv_k; o1.w = acc[7] * inv_k;
        float4* op = reinterpret_cast<float4*>(
            out + (size_t)warp_global * C + cq * 8);
        op[0] = o0;
        op[1] = o1;
    }
}

extern "C" void kernel_launch(void* const* d_in, const int* in_sizes, int n_in,
                              void* d_out, int out_size)
{
    // Select inputs by element count (ordering-proof):
    //   x:   B*N*C = 4,194,304 ; idx: B*N*K = 2,097,152
    const float* x = nullptr;
    const int* idx = nullptr;
    for (int i = 0; i < n_in; i++) {
        if (in_sizes[i] == B * N * C) x = (const float*)d_in[i];
        else if (in_sizes[i] == B * N * K) idx = (const int*)d_in[i];
    }
    if (!x) x = (const float*)d_in[0];
    if (!idx) idx = (const int*)d_in[1];
    float* out = (float*)d_out;

    // Stage 1: fp32 -> fp16 table
    const int cvt_threads = (B * N * C) / 8;               // 524288
    cvt_kernel<<<cvt_threads / 256, 256>>>(x);

    // Stage 2: gather-mean, one warp per point
    const int total_warps = B * N;                          // 65536
    gap_f16_kernel<<<(total_warps * 32) / 256, 256>>>(idx, out);
}

// round 12
// speedup vs baseline: 1.7121x; 1.0904x over previous
#include <cuda_runtime.h>
#include <cuda_fp16.h>
#include <cstdint>

// GAPooling: out[b,n,c] = (1/K) * sum_k x[b, idx[b,n,k], c]
// x [16,4096,64] fp32, idx [16,4096,32] int32, out fp32.
//
// Stage 1: x -> fp16 table (8 MB). Row = 128 B = exactly one L1 line.
// Stage 2: warp per point; 8x LDG.128 gathers (4 whole rows each -- the
//          wavefront-optimal shape: 1 line per gathered row, max bytes per
//          LDG instruction), per-lane idx loads (the warp's whole index
//          stream lives in one 128 B line; zero SHFL on the LSU/MIO path),
//          hadd2 chains of 4 with fp32 spill, butterfly reduce over the 4
//          row-slots, coalesced fp32 store.
// Preferred-carveout 0 -> maximize L1D (smem unused).
// Flat launch: chunk-pipelining (R10) and evict policies (R11) both lost.

static constexpr int B = 16;
static constexpr int N = 4096;
static constexpr int C = 64;
static constexpr int K = 32;

__device__ __half g_xh[(size_t)B * N * C];   // 8 MB fp16 table

__global__ __launch_bounds__(256) void cvt_kernel(const float* __restrict__ x)
{
    const int t = blockIdx.x * blockDim.x + threadIdx.x;   // B*N*C/8 threads
    const float4* __restrict__ xi = reinterpret_cast<const float4*>(x);
    float4 a = xi[2 * t];
    float4 b = xi[2 * t + 1];
    __half2 h[4];
    h[0] = __floats2half2_rn(a.x, a.y);
    h[1] = __floats2half2_rn(a.z, a.w);
    h[2] = __floats2half2_rn(b.x, b.y);
    h[3] = __floats2half2_rn(b.z, b.w);
    reinterpret_cast<uint4*>(g_xh)[t] = *reinterpret_cast<uint4*>(h);
}

__global__ __launch_bounds__(256) void gap_f16_kernel(
    const int* __restrict__ idx,
    float* __restrict__ out)
{
    const int warp_global = (blockIdx.x * blockDim.x + threadIdx.x) >> 5;
    const int lane = threadIdx.x & 31;

    const int b  = warp_global >> 12;          // N = 4096 = 2^12
    const int r  = lane >> 3;                  // 0..3  (row slot within LDG)
    const int cq = lane & 7;                   // 0..7  (16 B channel chunk)

    // This lane's index stream: positions r, r+4, ..., r+28. One 128 B line.
    const int* __restrict__ iw = idx + (size_t)warp_global * K + r;

    const __half* __restrict__ xb = g_xh + (size_t)b * N * C + cq * 8;

    float acc[8];
    #pragma unroll
    for (int c = 0; c < 8; c++) acc[c] = 0.f;

    #pragma unroll
    for (int blk = 0; blk < 2; blk++) {
        __half2 hacc[4];
        #pragma unroll
        for (int q = 0; q < 4; q++) hacc[q] = __half2half2(__ushort_as_half(0));

        #pragma unroll
        for (int i = 0; i < 4; i++) {
            const int j = __ldg(iw + (blk * 4 + i) * 4);   // slot r, quad i
            const float4 raw = *reinterpret_cast<const float4*>(
                xb + (size_t)j * C);                        // 16 B = 8 halves
            const __half2* h2 = reinterpret_cast<const __half2*>(&raw);
            #pragma unroll
            for (int q = 0; q < 4; q++)
                hacc[q] = __hadd2(hacc[q], h2[q]);
        }

        #pragma unroll
        for (int q = 0; q < 4; q++) {
            const float2 f = __half22float2(hacc[q]);
            acc[2 * q]     += f.x;
            acc[2 * q + 1] += f.y;
        }
    }

    // reduce the 4 r-groups (lane bits 3,4) in fp32
    #pragma unroll
    for (int c = 0; c < 8; c++) {
        acc[c] += __shfl_xor_sync(0xffffffffu, acc[c], 8);
        acc[c] += __shfl_xor_sync(0xffffffffu, acc[c], 16);
    }

    if (r == 0) {
        const float inv_k = 1.0f / (float)K;
        float4 o0, o1;
        o0.x = acc[0] * inv_k; o0.y = acc[1] * inv_k;
        o0.z = acc[2] * inv_k; o0.w = acc[3] * inv_k;
        o1.x = acc[4] * inv_k; o1.y = acc[5] * inv_k;
        o1.z = acc[6] * inv_k; o1.w = acc[7] * inv_k;
        float4* op = reinterpret_cast<float4*>(
            out + (size_t)warp_global * C + cq * 8);
        op[0] = o0;
        op[1] = o1;
    }
}

extern "C" void kernel_launch(void* const* d_in, const int* in_sizes, int n_in,
                              void* d_out, int out_size)
{
    // Select inputs by element count (ordering-proof):
    //   x:   B*N*C = 4,194,304 ; idx: B*N*K = 2,097,152
    const float* x = nullptr;
    const int* idx = nullptr;
    for (int i = 0; i < n_in; i++) {
        if (in_sizes[i] == B * N * C) x = (const float*)d_in[i];
        else if (in_sizes[i] == B * N * K) idx = (const int*)d_in[i];
    }
    if (!x) x = (const float*)d_in[0];
    if (!idx) idx = (const int*)d_in[1];
    float* out = (float*)d_out;

    // One-time: request 0% smem carveout -> maximum L1D for the gather.
    static bool attr_done = false;
    if (!attr_done) {
        cudaFuncSetAttribute(gap_f16_kernel,
                             cudaFuncAttributePreferredSharedMemoryCarveout, 0);
        attr_done = true;
    }

    // Stage 1: fp32 -> fp16 table
    const int cvt_threads = (B * N * C) / 8;               // 524288
    cvt_kernel<<<cvt_threads / 256, 256>>>(x);

    // Stage 2: gather-mean, one warp per point (exact grid, no tail)
    const int total_warps = B * N;                          // 65536
    gap_f16_kernel<<<(total_warps * 32) / 256, 256>>>(idx, out);
}